// round 6
// baseline (speedup 1.0000x reference)
#include <cuda_runtime.h>
#include <cuda_bf16.h>
#include <cstdint>

#define N_NODES 50000
#define MAXE    1600000
#define MAXF    256

// Static scratch (allocation-free rule).
__device__ float g_h[(size_t)N_NODES * MAXF];
__device__ float g_agg[(size_t)N_NODES * MAXF];
__device__ float g_act[(size_t)N_NODES * MAXF];
__device__ float g_deg[N_NODES];
__device__ float g_dinv[N_NODES];
__device__ float g_norm[MAXE];
__device__ int   g_src[MAXE];
__device__ int   g_dst[MAXE];

// ---------------- prep kernels ----------------

__global__ void deg_init_kernel(float* deg) {
    int i = blockIdx.x * blockDim.x + threadIdx.x;
    if (i < N_NODES) deg[i] = 1.0f;  // self-loop
}

// edge_index is int32 (JAX x64 disabled: jnp.int64 request silently yields int32).
__global__ void edge_prep_kernel(const int* __restrict__ ei,
                                 int* __restrict__ src, int* __restrict__ dst,
                                 float* __restrict__ deg, int E) {
    int e = blockIdx.x * blockDim.x + threadIdx.x;
    if (e >= E) return;
    int s = ei[e];
    int d = ei[E + e];
    if ((unsigned)s >= N_NODES) s = 0;  // defensive: never OOB
    if ((unsigned)d >= N_NODES) d = 0;
    src[e] = s;
    dst[e] = d;
    atomicAdd(&deg[d], 1.0f);
}

__global__ void dinv_kernel(const float* __restrict__ deg, float* __restrict__ dinv) {
    int i = blockIdx.x * blockDim.x + threadIdx.x;
    if (i < N_NODES) dinv[i] = rsqrtf(deg[i]);
}

__global__ void norm_kernel(const int* __restrict__ src, const int* __restrict__ dst,
                            const float* __restrict__ dinv, float* __restrict__ norm, int E) {
    int e = blockIdx.x * blockDim.x + threadIdx.x;
    if (e >= E) return;
    norm[e] = dinv[src[e]] * dinv[dst[e]];
}

// ---------------- GEMM: C[N,M] = A[N,K] @ B[K,M] ----------------

template <int BM, int BN, int BK, int TM, int TN>
__global__ void gemm_kernel(const float* __restrict__ A, const float* __restrict__ B,
                            float* __restrict__ C, int N, int K, int M) {
    constexpr int THREADS = (BM / TM) * (BN / TN);
    __shared__ float As[BK][BM];
    __shared__ float Bs[BK][BN];

    const int tid = threadIdx.x;
    const int tx = tid % (BN / TN);
    const int ty = tid / (BN / TN);
    const int rowBase = blockIdx.y * BM;
    const int colBase = blockIdx.x * BN;

    float acc[TM][TN];
#pragma unroll
    for (int i = 0; i < TM; i++)
#pragma unroll
        for (int j = 0; j < TN; j++) acc[i][j] = 0.0f;

    for (int k0 = 0; k0 < K; k0 += BK) {
#pragma unroll
        for (int i = tid; i < BM * BK; i += THREADS) {
            int m = i / BK;
            int k = i % BK;
            int r = rowBase + m;
            As[k][m] = (r < N) ? A[(size_t)r * K + k0 + k] : 0.0f;
        }
#pragma unroll
        for (int i = tid; i < BK * BN; i += THREADS) {
            int k = i / BN;
            int n = i % BN;
            Bs[k][n] = B[(size_t)(k0 + k) * M + colBase + n];
        }
        __syncthreads();

#pragma unroll
        for (int k = 0; k < BK; k++) {
            float aR[TM], bR[TN];
#pragma unroll
            for (int i = 0; i < TM; i++) aR[i] = As[k][ty * TM + i];
#pragma unroll
            for (int j = 0; j < TN; j++) bR[j] = Bs[k][tx * TN + j];
#pragma unroll
            for (int i = 0; i < TM; i++)
#pragma unroll
                for (int j = 0; j < TN; j++) acc[i][j] += aR[i] * bR[j];
        }
        __syncthreads();
    }

#pragma unroll
    for (int i = 0; i < TM; i++) {
        int r = rowBase + ty * TM + i;
        if (r >= N) continue;
#pragma unroll
        for (int j = 0; j < TN; j++) {
            C[(size_t)r * M + colBase + tx * TN + j] = acc[i][j];
        }
    }
}

// ---------------- prefill: agg = h * dinv^2 + b (self-loop + bias) ----------------

__global__ void prefill_kernel(const float* __restrict__ h, const float* __restrict__ dinv,
                               const float* __restrict__ b, float* __restrict__ agg, int M) {
    unsigned idx = blockIdx.x * blockDim.x + threadIdx.x;
    unsigned total = (unsigned)N_NODES * (unsigned)M;
    if (idx >= total) return;
    int i = idx / M;
    int f = idx % M;
    float di = dinv[i];
    agg[idx] = h[idx] * (di * di) + b[f];
}

// ---------------- scatter: agg[dst] += h[src] * norm ----------------

__global__ void scatter_kernel(const float* __restrict__ h, const float* __restrict__ norm,
                               const int* __restrict__ src, const int* __restrict__ dst,
                               float* __restrict__ agg, int E, int M) {
    const int Mq = M >> 2;
    unsigned idx = blockIdx.x * blockDim.x + threadIdx.x;
    unsigned total = (unsigned)E * (unsigned)Mq;
    if (idx >= total) return;
    int e = idx / Mq;
    int f = (idx % Mq) << 2;
    float nv = norm[e];
    int s = src[e];
    int d = dst[e];
    float4 v = *reinterpret_cast<const float4*>(h + (size_t)s * M + f);
    float* ap = agg + (size_t)d * M + f;
    atomicAdd(ap + 0, v.x * nv);
    atomicAdd(ap + 1, v.y * nv);
    atomicAdd(ap + 2, v.z * nv);
    atomicAdd(ap + 3, v.w * nv);
}

// ---------------- relu: out = max(agg, 0) ----------------

__global__ void relu_kernel(const float* __restrict__ agg, float* __restrict__ out, unsigned total) {
    unsigned idx = blockIdx.x * blockDim.x + threadIdx.x;
    if (idx >= total) return;
    out[idx] = fmaxf(agg[idx], 0.0f);
}

// ---------------- host-side layer driver ----------------

static void run_gemm(const float* A, const float* B, float* C, int N, int K, int M) {
    if (M % 64 == 0) {
        constexpr int BM = 64, BN = 64, BK = 16, TM = 4, TN = 4;
        dim3 grid(M / BN, (N + BM - 1) / BM);
        gemm_kernel<BM, BN, BK, TM, TN><<<grid, (BM / TM) * (BN / TN)>>>(A, B, C, N, K, M);
    } else {  // M == 32
        constexpr int BM = 64, BN = 32, BK = 16, TM = 4, TN = 4;
        dim3 grid(M / BN, (N + BM - 1) / BM);
        gemm_kernel<BM, BN, BK, TM, TN><<<grid, (BM / TM) * (BN / TN)>>>(A, B, C, N, K, M);
    }
}

static void run_layer(const float* act_in, const float* W, const float* b, float* act_out,
                      float* h, float* agg, const float* dinv, const float* norm,
                      const int* src, const int* dst, int E, int K, int M) {
    run_gemm(act_in, W, h, N_NODES, K, M);
    {
        unsigned total = (unsigned)N_NODES * (unsigned)M;
        prefill_kernel<<<(total + 255) / 256, 256>>>(h, dinv, b, agg, M);
    }
    {
        unsigned total = (unsigned)E * (unsigned)(M / 4);
        scatter_kernel<<<(total + 255) / 256, 256>>>(h, norm, src, dst, agg, E, M);
    }
    {
        unsigned total = (unsigned)N_NODES * (unsigned)M;
        relu_kernel<<<(total + 255) / 256, 256>>>(agg, act_out, total);
    }
}

extern "C" void kernel_launch(void* const* d_in, const int* in_sizes, int n_in,
                              void* d_out, int out_size) {
    const float* x  = (const float*)d_in[0];
    const int*   ei = (const int*)d_in[1];
    const float* W1 = (const float*)d_in[2];
    const float* b1 = (const float*)d_in[3];
    const float* W2 = (const float*)d_in[4];
    const float* b2 = (const float*)d_in[5];
    const float* W3 = (const float*)d_in[6];
    const float* b3 = (const float*)d_in[7];
    const float* W4 = (const float*)d_in[8];
    const float* b4 = (const float*)d_in[9];

    const int E = in_sizes[1] / 2;

    float *h, *agg, *act, *deg, *dinv, *norm;
    int *src, *dst;
    cudaGetSymbolAddress((void**)&h, g_h);
    cudaGetSymbolAddress((void**)&agg, g_agg);
    cudaGetSymbolAddress((void**)&act, g_act);
    cudaGetSymbolAddress((void**)&deg, g_deg);
    cudaGetSymbolAddress((void**)&dinv, g_dinv);
    cudaGetSymbolAddress((void**)&norm, g_norm);
    cudaGetSymbolAddress((void**)&src, g_src);
    cudaGetSymbolAddress((void**)&dst, g_dst);

    // --- prep: degrees + per-edge norms ---
    deg_init_kernel<<<(N_NODES + 255) / 256, 256>>>(deg);
    edge_prep_kernel<<<(E + 255) / 256, 256>>>(ei, src, dst, deg, E);
    dinv_kernel<<<(N_NODES + 255) / 256, 256>>>(deg, dinv);
    norm_kernel<<<(E + 255) / 256, 256>>>(src, dst, dinv, norm, E);

    // --- 4 GCN layers ---
    run_layer(x,   W1, b1, act, h, agg, dinv, norm, src, dst, E, 128, 256);
    run_layer(act, W2, b2, act, h, agg, dinv, norm, src, dst, E, 256, 128);
    run_layer(act, W3, b3, act, h, agg, dinv, norm, src, dst, E, 128, 64);
    run_layer(act, W4, b4, (float*)d_out, h, agg, dinv, norm, src, dst, E, 64, 32);
}

// round 7
// speedup vs baseline: 1.0000x; 1.0000x over previous
#include <cuda_runtime.h>
#include <cuda_bf16.h>
#include <cstdint>

#define N_NODES 50000
#define MAXE    1600000
#define MAXF    256

// Static scratch (allocation-free rule).
__device__ float g_h[(size_t)N_NODES * MAXF];
__device__ float g_agg[(size_t)N_NODES * MAXF];
__device__ float g_act[(size_t)N_NODES * MAXF];
__device__ float g_deg[N_NODES];
__device__ float g_dinv[N_NODES];
__device__ float g_norm[MAXE];
__device__ int   g_src[MAXE];
__device__ int   g_dst[MAXE];

// ---------------- prep kernels ----------------

__global__ void deg_init_kernel(float* deg) {
    int i = blockIdx.x * blockDim.x + threadIdx.x;
    if (i < N_NODES) deg[i] = 1.0f;  // self-loop
}

// edge_index is int32 (JAX x64 disabled: jnp.int64 request silently yields int32).
__global__ void edge_prep_kernel(const int* __restrict__ ei,
                                 int* __restrict__ src, int* __restrict__ dst,
                                 float* __restrict__ deg, int E) {
    int e = blockIdx.x * blockDim.x + threadIdx.x;
    if (e >= E) return;
    int s = ei[e];
    int d = ei[E + e];
    if ((unsigned)s >= N_NODES) s = 0;  // defensive: never OOB
    if ((unsigned)d >= N_NODES) d = 0;
    src[e] = s;
    dst[e] = d;
    atomicAdd(&deg[d], 1.0f);
}

__global__ void dinv_kernel(const float* __restrict__ deg, float* __restrict__ dinv) {
    int i = blockIdx.x * blockDim.x + threadIdx.x;
    if (i < N_NODES) dinv[i] = rsqrtf(deg[i]);
}

__global__ void norm_kernel(const int* __restrict__ src, const int* __restrict__ dst,
                            const float* __restrict__ dinv, float* __restrict__ norm, int E) {
    int e = blockIdx.x * blockDim.x + threadIdx.x;
    if (e >= E) return;
    norm[e] = dinv[src[e]] * dinv[dst[e]];
}

// ---------------- GEMM: C[N,M] = A[N,K] @ B[K,M] ----------------

template <int BM, int BN, int BK, int TM, int TN>
__global__ void gemm_kernel(const float* __restrict__ A, const float* __restrict__ B,
                            float* __restrict__ C, int N, int K, int M) {
    constexpr int THREADS = (BM / TM) * (BN / TN);
    __shared__ float As[BK][BM];
    __shared__ float Bs[BK][BN];

    const int tid = threadIdx.x;
    const int tx = tid % (BN / TN);
    const int ty = tid / (BN / TN);
    const int rowBase = blockIdx.y * BM;
    const int colBase = blockIdx.x * BN;

    float acc[TM][TN];
#pragma unroll
    for (int i = 0; i < TM; i++)
#pragma unroll
        for (int j = 0; j < TN; j++) acc[i][j] = 0.0f;

    for (int k0 = 0; k0 < K; k0 += BK) {
#pragma unroll
        for (int i = tid; i < BM * BK; i += THREADS) {
            int m = i / BK;
            int k = i % BK;
            int r = rowBase + m;
            As[k][m] = (r < N) ? A[(size_t)r * K + k0 + k] : 0.0f;
        }
#pragma unroll
        for (int i = tid; i < BK * BN; i += THREADS) {
            int k = i / BN;
            int n = i % BN;
            Bs[k][n] = B[(size_t)(k0 + k) * M + colBase + n];
        }
        __syncthreads();

#pragma unroll
        for (int k = 0; k < BK; k++) {
            float aR[TM], bR[TN];
#pragma unroll
            for (int i = 0; i < TM; i++) aR[i] = As[k][ty * TM + i];
#pragma unroll
            for (int j = 0; j < TN; j++) bR[j] = Bs[k][tx * TN + j];
#pragma unroll
            for (int i = 0; i < TM; i++)
#pragma unroll
                for (int j = 0; j < TN; j++) acc[i][j] += aR[i] * bR[j];
        }
        __syncthreads();
    }

#pragma unroll
    for (int i = 0; i < TM; i++) {
        int r = rowBase + ty * TM + i;
        if (r >= N) continue;
#pragma unroll
        for (int j = 0; j < TN; j++) {
            C[(size_t)r * M + colBase + tx * TN + j] = acc[i][j];
        }
    }
}

// ---------------- prefill: agg = h * dinv^2 + b (self-loop + bias) ----------------

__global__ void prefill_kernel(const float* __restrict__ h, const float* __restrict__ dinv,
                               const float* __restrict__ b, float* __restrict__ agg, int M) {
    unsigned idx = blockIdx.x * blockDim.x + threadIdx.x;
    unsigned total = (unsigned)N_NODES * (unsigned)M;
    if (idx >= total) return;
    int i = idx / M;
    int f = idx % M;
    float di = dinv[i];
    agg[idx] = h[idx] * (di * di) + b[f];
}

// ---------------- scatter: agg[dst] += h[src] * norm ----------------

__global__ void scatter_kernel(const float* __restrict__ h, const float* __restrict__ norm,
                               const int* __restrict__ src, const int* __restrict__ dst,
                               float* __restrict__ agg, int E, int M) {
    const int Mq = M >> 2;
    unsigned idx = blockIdx.x * blockDim.x + threadIdx.x;
    unsigned total = (unsigned)E * (unsigned)Mq;
    if (idx >= total) return;
    int e = idx / Mq;
    int f = (idx % Mq) << 2;
    float nv = norm[e];
    int s = src[e];
    int d = dst[e];
    float4 v = *reinterpret_cast<const float4*>(h + (size_t)s * M + f);
    float* ap = agg + (size_t)d * M + f;
    atomicAdd(ap + 0, v.x * nv);
    atomicAdd(ap + 1, v.y * nv);
    atomicAdd(ap + 2, v.z * nv);
    atomicAdd(ap + 3, v.w * nv);
}

// ---------------- relu: out = max(agg, 0) ----------------

__global__ void relu_kernel(const float* __restrict__ agg, float* __restrict__ out, unsigned total) {
    unsigned idx = blockIdx.x * blockDim.x + threadIdx.x;
    if (idx >= total) return;
    out[idx] = fmaxf(agg[idx], 0.0f);
}

// ---------------- host-side layer driver ----------------

static void run_gemm(const float* A, const float* B, float* C, int N, int K, int M) {
    if (M % 64 == 0) {
        constexpr int BM = 64, BN = 64, BK = 16, TM = 4, TN = 4;
        dim3 grid(M / BN, (N + BM - 1) / BM);
        gemm_kernel<BM, BN, BK, TM, TN><<<grid, (BM / TM) * (BN / TN)>>>(A, B, C, N, K, M);
    } else {  // M == 32
        constexpr int BM = 64, BN = 32, BK = 16, TM = 4, TN = 4;
        dim3 grid(M / BN, (N + BM - 1) / BM);
        gemm_kernel<BM, BN, BK, TM, TN><<<grid, (BM / TM) * (BN / TN)>>>(A, B, C, N, K, M);
    }
}

static void run_layer(const float* act_in, const float* W, const float* b, float* act_out,
                      float* h, float* agg, const float* dinv, const float* norm,
                      const int* src, const int* dst, int E, int K, int M) {
    run_gemm(act_in, W, h, N_NODES, K, M);
    {
        unsigned total = (unsigned)N_NODES * (unsigned)M;
        prefill_kernel<<<(total + 255) / 256, 256>>>(h, dinv, b, agg, M);
    }
    {
        unsigned total = (unsigned)E * (unsigned)(M / 4);
        scatter_kernel<<<(total + 255) / 256, 256>>>(h, norm, src, dst, agg, E, M);
    }
    {
        unsigned total = (unsigned)N_NODES * (unsigned)M;
        relu_kernel<<<(total + 255) / 256, 256>>>(agg, act_out, total);
    }
}

extern "C" void kernel_launch(void* const* d_in, const int* in_sizes, int n_in,
                              void* d_out, int out_size) {
    const float* x  = (const float*)d_in[0];
    const int*   ei = (const int*)d_in[1];
    const float* W1 = (const float*)d_in[2];
    const float* b1 = (const float*)d_in[3];
    const float* W2 = (const float*)d_in[4];
    const float* b2 = (const float*)d_in[5];
    const float* W3 = (const float*)d_in[6];
    const float* b3 = (const float*)d_in[7];
    const float* W4 = (const float*)d_in[8];
    const float* b4 = (const float*)d_in[9];

    const int E = in_sizes[1] / 2;

    float *h, *agg, *act, *deg, *dinv, *norm;
    int *src, *dst;
    cudaGetSymbolAddress((void**)&h, g_h);
    cudaGetSymbolAddress((void**)&agg, g_agg);
    cudaGetSymbolAddress((void**)&act, g_act);
    cudaGetSymbolAddress((void**)&deg, g_deg);
    cudaGetSymbolAddress((void**)&dinv, g_dinv);
    cudaGetSymbolAddress((void**)&norm, g_norm);
    cudaGetSymbolAddress((void**)&src, g_src);
    cudaGetSymbolAddress((void**)&dst, g_dst);

    // --- prep: degrees + per-edge norms ---
    deg_init_kernel<<<(N_NODES + 255) / 256, 256>>>(deg);
    edge_prep_kernel<<<(E + 255) / 256, 256>>>(ei, src, dst, deg, E);
    dinv_kernel<<<(N_NODES + 255) / 256, 256>>>(deg, dinv);
    norm_kernel<<<(E + 255) / 256, 256>>>(src, dst, dinv, norm, E);

    // --- 4 GCN layers ---
    run_layer(x,   W1, b1, act, h, agg, dinv, norm, src, dst, E, 128, 256);
    run_layer(act, W2, b2, act, h, agg, dinv, norm, src, dst, E, 256, 128);
    run_layer(act, W3, b3, act, h, agg, dinv, norm, src, dst, E, 128, 64);
    run_layer(act, W4, b4, (float*)d_out, h, agg, dinv, norm, src, dst, E, 64, 32);
}

// round 8
// speedup vs baseline: 1.0081x; 1.0081x over previous
#include <cuda_runtime.h>
#include <cuda_bf16.h>
#include <cstdint>

#define N_NODES 50000
#define MAXE    1600000
#define MAXF    256

// Static scratch (allocation-free rule).
__device__ float g_h[(size_t)N_NODES * MAXF];
__device__ float g_agg[(size_t)N_NODES * MAXF];
__device__ float g_act[(size_t)N_NODES * MAXF];
__device__ float g_deg[N_NODES];
__device__ float g_dinv[N_NODES];
__device__ float g_norm[MAXE];
__device__ int   g_src[MAXE];
__device__ int   g_dst[MAXE];

// ---------------- prep kernels ----------------

__global__ void deg_init_kernel(float* deg) {
    int i = blockIdx.x * blockDim.x + threadIdx.x;
    if (i < N_NODES) deg[i] = 1.0f;  // self-loop
}

// edge_index is int32 (JAX x64 disabled: jnp.int64 request silently yields int32).
__global__ void edge_prep_kernel(const int* __restrict__ ei,
                                 int* __restrict__ src, int* __restrict__ dst,
                                 float* __restrict__ deg, int E) {
    int e = blockIdx.x * blockDim.x + threadIdx.x;
    if (e >= E) return;
    int s = ei[e];
    int d = ei[E + e];
    if ((unsigned)s >= N_NODES) s = 0;  // defensive: never OOB
    if ((unsigned)d >= N_NODES) d = 0;
    src[e] = s;
    dst[e] = d;
    atomicAdd(&deg[d], 1.0f);
}

__global__ void dinv_kernel(const float* __restrict__ deg, float* __restrict__ dinv) {
    int i = blockIdx.x * blockDim.x + threadIdx.x;
    if (i < N_NODES) dinv[i] = rsqrtf(deg[i]);
}

__global__ void norm_kernel(const int* __restrict__ src, const int* __restrict__ dst,
                            const float* __restrict__ dinv, float* __restrict__ norm, int E) {
    int e = blockIdx.x * blockDim.x + threadIdx.x;
    if (e >= E) return;
    norm[e] = dinv[src[e]] * dinv[dst[e]];
}

// ---------------- GEMM: C[N,M] = A[N,K] @ B[K,M] ----------------

template <int BM, int BN, int BK, int TM, int TN>
__global__ void gemm_kernel(const float* __restrict__ A, const float* __restrict__ B,
                            float* __restrict__ C, int N, int K, int M) {
    constexpr int THREADS = (BM / TM) * (BN / TN);
    __shared__ float As[BK][BM];
    __shared__ float Bs[BK][BN];

    const int tid = threadIdx.x;
    const int tx = tid % (BN / TN);
    const int ty = tid / (BN / TN);
    const int rowBase = blockIdx.y * BM;
    const int colBase = blockIdx.x * BN;

    float acc[TM][TN];
#pragma unroll
    for (int i = 0; i < TM; i++)
#pragma unroll
        for (int j = 0; j < TN; j++) acc[i][j] = 0.0f;

    for (int k0 = 0; k0 < K; k0 += BK) {
#pragma unroll
        for (int i = tid; i < BM * BK; i += THREADS) {
            int m = i / BK;
            int k = i % BK;
            int r = rowBase + m;
            As[k][m] = (r < N) ? A[(size_t)r * K + k0 + k] : 0.0f;
        }
#pragma unroll
        for (int i = tid; i < BK * BN; i += THREADS) {
            int k = i / BN;
            int n = i % BN;
            Bs[k][n] = B[(size_t)(k0 + k) * M + colBase + n];
        }
        __syncthreads();

#pragma unroll
        for (int k = 0; k < BK; k++) {
            float aR[TM], bR[TN];
#pragma unroll
            for (int i = 0; i < TM; i++) aR[i] = As[k][ty * TM + i];
#pragma unroll
            for (int j = 0; j < TN; j++) bR[j] = Bs[k][tx * TN + j];
#pragma unroll
            for (int i = 0; i < TM; i++)
#pragma unroll
                for (int j = 0; j < TN; j++) acc[i][j] += aR[i] * bR[j];
        }
        __syncthreads();
    }

#pragma unroll
    for (int i = 0; i < TM; i++) {
        int r = rowBase + ty * TM + i;
        if (r >= N) continue;
#pragma unroll
        for (int j = 0; j < TN; j++) {
            C[(size_t)r * M + colBase + tx * TN + j] = acc[i][j];
        }
    }
}

// ---------------- prefill: agg = h * dinv^2 + b (self-loop + bias) ----------------

__global__ void prefill_kernel(const float* __restrict__ h, const float* __restrict__ dinv,
                               const float* __restrict__ b, float* __restrict__ agg, int M) {
    unsigned idx = blockIdx.x * blockDim.x + threadIdx.x;
    unsigned total = (unsigned)N_NODES * (unsigned)M;
    if (idx >= total) return;
    int i = idx / M;
    int f = idx % M;
    float di = dinv[i];
    agg[idx] = h[idx] * (di * di) + b[f];
}

// ---------------- scatter: agg[dst] += h[src] * norm ----------------

__global__ void scatter_kernel(const float* __restrict__ h, const float* __restrict__ norm,
                               const int* __restrict__ src, const int* __restrict__ dst,
                               float* __restrict__ agg, int E, int M) {
    const int Mq = M >> 2;
    unsigned idx = blockIdx.x * blockDim.x + threadIdx.x;
    unsigned total = (unsigned)E * (unsigned)Mq;
    if (idx >= total) return;
    int e = idx / Mq;
    int f = (idx % Mq) << 2;
    float nv = norm[e];
    int s = src[e];
    int d = dst[e];
    float4 v = *reinterpret_cast<const float4*>(h + (size_t)s * M + f);
    float* ap = agg + (size_t)d * M + f;
    atomicAdd(ap + 0, v.x * nv);
    atomicAdd(ap + 1, v.y * nv);
    atomicAdd(ap + 2, v.z * nv);
    atomicAdd(ap + 3, v.w * nv);
}

// ---------------- relu: out = max(agg, 0) ----------------

__global__ void relu_kernel(const float* __restrict__ agg, float* __restrict__ out, unsigned total) {
    unsigned idx = blockIdx.x * blockDim.x + threadIdx.x;
    if (idx >= total) return;
    out[idx] = fmaxf(agg[idx], 0.0f);
}

// ---------------- host-side layer driver ----------------

static void run_gemm(const float* A, const float* B, float* C, int N, int K, int M) {
    if (M % 64 == 0) {
        constexpr int BM = 64, BN = 64, BK = 16, TM = 4, TN = 4;
        dim3 grid(M / BN, (N + BM - 1) / BM);
        gemm_kernel<BM, BN, BK, TM, TN><<<grid, (BM / TM) * (BN / TN)>>>(A, B, C, N, K, M);
    } else {  // M == 32
        constexpr int BM = 64, BN = 32, BK = 16, TM = 4, TN = 4;
        dim3 grid(M / BN, (N + BM - 1) / BM);
        gemm_kernel<BM, BN, BK, TM, TN><<<grid, (BM / TM) * (BN / TN)>>>(A, B, C, N, K, M);
    }
}

static void run_layer(const float* act_in, const float* W, const float* b, float* act_out,
                      float* h, float* agg, const float* dinv, const float* norm,
                      const int* src, const int* dst, int E, int K, int M) {
    run_gemm(act_in, W, h, N_NODES, K, M);
    {
        unsigned total = (unsigned)N_NODES * (unsigned)M;
        prefill_kernel<<<(total + 255) / 256, 256>>>(h, dinv, b, agg, M);
    }
    {
        unsigned total = (unsigned)E * (unsigned)(M / 4);
        scatter_kernel<<<(total + 255) / 256, 256>>>(h, norm, src, dst, agg, E, M);
    }
    {
        unsigned total = (unsigned)N_NODES * (unsigned)M;
        relu_kernel<<<(total + 255) / 256, 256>>>(agg, act_out, total);
    }
}

extern "C" void kernel_launch(void* const* d_in, const int* in_sizes, int n_in,
                              void* d_out, int out_size) {
    const float* x  = (const float*)d_in[0];
    const int*   ei = (const int*)d_in[1];
    const float* W1 = (const float*)d_in[2];
    const float* b1 = (const float*)d_in[3];
    const float* W2 = (const float*)d_in[4];
    const float* b2 = (const float*)d_in[5];
    const float* W3 = (const float*)d_in[6];
    const float* b3 = (const float*)d_in[7];
    const float* W4 = (const float*)d_in[8];
    const float* b4 = (const float*)d_in[9];

    const int E = in_sizes[1] / 2;

    float *h, *agg, *act, *deg, *dinv, *norm;
    int *src, *dst;
    cudaGetSymbolAddress((void**)&h, g_h);
    cudaGetSymbolAddress((void**)&agg, g_agg);
    cudaGetSymbolAddress((void**)&act, g_act);
    cudaGetSymbolAddress((void**)&deg, g_deg);
    cudaGetSymbolAddress((void**)&dinv, g_dinv);
    cudaGetSymbolAddress((void**)&norm, g_norm);
    cudaGetSymbolAddress((void**)&src, g_src);
    cudaGetSymbolAddress((void**)&dst, g_dst);

    // --- prep: degrees + per-edge norms ---
    deg_init_kernel<<<(N_NODES + 255) / 256, 256>>>(deg);
    edge_prep_kernel<<<(E + 255) / 256, 256>>>(ei, src, dst, deg, E);
    dinv_kernel<<<(N_NODES + 255) / 256, 256>>>(deg, dinv);
    norm_kernel<<<(E + 255) / 256, 256>>>(src, dst, dinv, norm, E);

    // --- 4 GCN layers ---
    run_layer(x,   W1, b1, act, h, agg, dinv, norm, src, dst, E, 128, 256);
    run_layer(act, W2, b2, act, h, agg, dinv, norm, src, dst, E, 256, 128);
    run_layer(act, W3, b3, act, h, agg, dinv, norm, src, dst, E, 128, 64);
    run_layer(act, W4, b4, (float*)d_out, h, agg, dinv, norm, src, dst, E, 64, 32);
}